// round 9
// baseline (speedup 1.0000x reference)
#include <cuda_runtime.h>
#include <cuda_bf16.h>
#include <cstdint>

// ============================================================================
// Problem constants
// ============================================================================
#define NROWS 8192
#define DIM   512
#define BM    128
#define BN    128
#define BK    64                 // bf16 elements per K-chunk (= 128 bytes/row)
#define KCH   (DIM / BK)         // 8 chunks
#define NSTAGE 3
#define NT    (NROWS / BM)       // 64 tiles per dim
#define NTRI  (NT * (NT + 1) / 2)          // 2080 upper-triangle tiles

#define TILE_BYTES  (BM * 128)         // 16384: 128 rows x 128B
#define STAGE_BYTES (2 * TILE_BYTES)   // A + B per stage = 32 KB

// SMEM layout (dynamic):
//   [0,512)     row norms (128 f32)
//   [512,1024)  col norms (128 f32)
//   [1024, ...) 3 stages x 32KB tiles; reused post-mainloop as the
//               128x129-f32 transpose buffer for the mirrored store (66 KB)
#define OFF_NR   0
#define OFF_NC   512
#define OFF_TILE 1024
#define SMEM_TOTAL (OFF_TILE + NSTAGE * STAGE_BYTES)   // 99328 bytes

// ============================================================================
// Static device scratch (allocation-free rule: __device__ globals)
// ============================================================================
__device__ __align__(1024) __nv_bfloat16 g_A[NROWS * DIM];   // 8 MB bf16 copy
__device__ float g_norm[NROWS];

// ============================================================================
// PTX helpers (portable: compile at compute_103)
// ============================================================================
__device__ __forceinline__ uint32_t smem_u32(const void* p) {
    uint32_t a;
    asm("{ .reg .u64 t; cvta.to.shared.u64 t, %1; cvt.u32.u64 %0, t; }"
        : "=r"(a) : "l"(p));
    return a;
}

__device__ __forceinline__ void ldmatrix_x4(uint32_t& r0, uint32_t& r1,
                                            uint32_t& r2, uint32_t& r3,
                                            uint32_t addr) {
    asm volatile("ldmatrix.sync.aligned.m8n8.x4.shared.b16 {%0,%1,%2,%3}, [%4];"
                 : "=r"(r0), "=r"(r1), "=r"(r2), "=r"(r3) : "r"(addr));
}

__device__ __forceinline__ void mma_bf16(float* c, const uint32_t* a,
                                         uint32_t b0, uint32_t b1) {
    asm volatile(
        "mma.sync.aligned.m16n8k16.row.col.f32.bf16.bf16.f32 "
        "{%0,%1,%2,%3}, {%4,%5,%6,%7}, {%8,%9}, {%0,%1,%2,%3};"
        : "+f"(c[0]), "+f"(c[1]), "+f"(c[2]), "+f"(c[3])
        : "r"(a[0]), "r"(a[1]), "r"(a[2]), "r"(a[3]), "r"(b0), "r"(b1));
}

// SW128-style swizzle: byte offset within a [rows][128B] tile
__device__ __forceinline__ uint32_t swz(uint32_t off) {
    return off ^ ((off >> 3) & 0x70);
}

// ============================================================================
// Prep: fp32 -> bf16 conversion + row norms. One block per row, 128 threads.
// ============================================================================
__global__ void __launch_bounds__(128) prep_kernel(const float* __restrict__ in) {
    int row = blockIdx.x, t = threadIdx.x;
    const float4 v = *reinterpret_cast<const float4*>(in + (size_t)row * DIM + t * 4);
    float s = v.x * v.x + v.y * v.y + v.z * v.z + v.w * v.w;

    __nv_bfloat162 p0 = __float22bfloat162_rn(make_float2(v.x, v.y));
    __nv_bfloat162 p1 = __float22bfloat162_rn(make_float2(v.z, v.w));
    uint32_t u0 = *reinterpret_cast<uint32_t*>(&p0);
    uint32_t u1 = *reinterpret_cast<uint32_t*>(&p1);
    *reinterpret_cast<uint2*>(&g_A[(size_t)row * DIM + t * 4]) = make_uint2(u0, u1);

    #pragma unroll
    for (int off = 16; off > 0; off >>= 1)
        s += __shfl_xor_sync(0xFFFFFFFFu, s, off);
    __shared__ float ss[4];
    if ((t & 31) == 0) ss[t >> 5] = s;
    __syncthreads();
    if (t == 0) g_norm[row] = sqrtf(ss[0] + ss[1] + ss[2] + ss[3]);
}

// ============================================================================
// Async stage loader: A tile (rows row0..+127) + B tile (rows col0..+127),
// each [128][64] bf16 = [128][128B], SW128 swizzled. 128 threads, 16B x8 each.
// ============================================================================
__device__ __forceinline__ void load_stage(uint32_t sb, int tid, int row0, int col0,
                                           int kc, int s) {
    uint32_t stage = sb + OFF_TILE + s * STAGE_BYTES;
    #pragma unroll
    for (int i = 0; i < 8; i++) {
        int idx = tid + i * 128;
        int r = idx >> 3, c = idx & 7;
        const void* g = (const char*)(g_A + (size_t)(row0 + r) * DIM + kc * BK) + c * 16;
        uint32_t off = swz((uint32_t)(r * 128 + c * 16));
        asm volatile("cp.async.cg.shared.global [%0], [%1], 16;\n"
                     :: "r"(stage + off), "l"(g));
    }
    #pragma unroll
    for (int i = 0; i < 8; i++) {
        int idx = tid + i * 128;
        int r = idx >> 3, c = idx & 7;
        const void* g = (const char*)(g_A + (size_t)(col0 + r) * DIM + kc * BK) + c * 16;
        uint32_t off = swz((uint32_t)(r * 128 + c * 16));
        asm volatile("cp.async.cg.shared.global [%0], [%1], 16;\n"
                     :: "r"(stage + TILE_BYTES + off), "l"(g));
    }
    asm volatile("cp.async.commit_group;\n" ::: "memory");
}

// ============================================================================
// Main GEMM + epilogue. Upper-triangle tiles only; mirror store for bi != bj.
// 128 threads = 4 warps (2 m x 2 n), 64x64 per warp (32 MMA / 8 ldmatrix).
// ============================================================================
__global__ void __launch_bounds__(128, 2) cosmat_kernel(float* __restrict__ out) {
    extern __shared__ char smem[];
    uint32_t sb = smem_u32(smem);
    const int tid = threadIdx.x;
    const int wid = tid >> 5, lane = tid & 31;
    const int warp_m = wid >> 1, warp_n = wid & 1;   // 2 x 2

    // --- decode linear block id -> upper-triangle tile (bi <= bj) ---
    const int t = blockIdx.x;
    int bi = (int)((2.0f * NT + 1.0f
                    - sqrtf((2.0f * NT + 1.0f) * (2.0f * NT + 1.0f) - 8.0f * t))
                   * 0.5f);
    while (bi > 0 && bi * (2 * NT - bi + 1) / 2 > t) bi--;
    while ((bi + 1) * (2 * NT - bi) / 2 <= t) bi++;
    const int bj = bi + (t - bi * (2 * NT - bi + 1) / 2);
    const int row0 = bi * BM, col0 = bj * BN;
    const bool mirror = (bi != bj);

    ((float*)(smem + OFF_NR))[tid] = g_norm[row0 + tid];
    ((float*)(smem + OFF_NC))[tid] = g_norm[col0 + tid];

    // prologue: fill first 2 stages
    load_stage(sb, tid, row0, col0, 0, 0);
    load_stage(sb, tid, row0, col0, 1, 1);

    float acc[4][8][4];
    #pragma unroll
    for (int i = 0; i < 4; i++)
        #pragma unroll
        for (int j = 0; j < 8; j++)
            #pragma unroll
            for (int k = 0; k < 4; k++) acc[i][j][k] = 0.0f;

    const int m0 = warp_m * 64;
    const int n0 = warp_n * 64;

    // per-lane fragment addressing (within-tile)
    const int a_row  = lane & 15;
    const int a_koff = ((lane >> 4) & 1) * 8;
    const int b_row  = (lane & 7) + ((lane >> 4) & 1) * 8;
    const int b_koff = ((lane >> 3) & 1) * 8;

    for (int kc = 0; kc < KCH; kc++) {
        int s = kc % NSTAGE;
        if (kc + 2 < KCH) load_stage(sb, tid, row0, col0, kc + 2, (kc + 2) % NSTAGE);

        if (kc < KCH - 2)       asm volatile("cp.async.wait_group 2;\n" ::: "memory");
        else if (kc == KCH - 2) asm volatile("cp.async.wait_group 1;\n" ::: "memory");
        else                    asm volatile("cp.async.wait_group 0;\n" ::: "memory");
        __syncthreads();

        const uint32_t sa  = sb + OFF_TILE + s * STAGE_BYTES;
        const uint32_t sbb = sa + TILE_BYTES;

        #pragma unroll
        for (int kq = 0; kq < 4; kq++) {
            const int kb_a = kq * 16 + a_koff;
            const int kb_b = kq * 16 + b_koff;

            uint32_t a[4][4];
            #pragma unroll
            for (int mt = 0; mt < 4; mt++) {
                uint32_t off = swz((uint32_t)((m0 + mt * 16 + a_row) * 128 + kb_a * 2));
                ldmatrix_x4(a[mt][0], a[mt][1], a[mt][2], a[mt][3], sa + off);
            }
            uint32_t b[4][4];
            #pragma unroll
            for (int p = 0; p < 4; p++) {
                uint32_t off = swz((uint32_t)((n0 + p * 16 + b_row) * 128 + kb_b * 2));
                ldmatrix_x4(b[p][0], b[p][1], b[p][2], b[p][3], sbb + off);
            }
            #pragma unroll
            for (int mt = 0; mt < 4; mt++) {
                #pragma unroll
                for (int p = 0; p < 4; p++) {
                    mma_bf16(acc[mt][2 * p],     a[mt], b[p][0], b[p][1]);
                    mma_bf16(acc[mt][2 * p + 1], a[mt], b[p][2], b[p][3]);
                }
            }
        }
        __syncthreads();   // also protects SMEM reuse as transpose buffer below
    }

    // ---- epilogue: cosine distance; direct store + (off-diag) mirror store ----
    const float* nr = (const float*)(smem + OFF_NR);
    const float* nc = (const float*)(smem + OFF_NC);
    float* tb = (float*)(smem + OFF_TILE);          // [128][129] f32 transpose buf
    const int lr = lane >> 2;
    const int lc = (lane & 3) * 2;

    #pragma unroll
    for (int mt = 0; mt < 4; mt++) {
        #pragma unroll
        for (int half = 0; half < 2; half++) {
            const int rloc = m0 + mt * 16 + lr + half * 8;
            const float ni = nr[rloc];
            const size_t rbase = (size_t)(row0 + rloc) * NROWS + col0;
            #pragma unroll
            for (int nt = 0; nt < 8; nt++) {
                const int cloc = n0 + nt * 8 + lc;
                const float nj0 = nc[cloc], nj1 = nc[cloc + 1];
                float2 v;
                v.x = 1.0f - acc[mt][nt][2 * half]     / fmaxf(ni * nj0, 1e-8f);
                v.y = 1.0f - acc[mt][nt][2 * half + 1] / fmaxf(ni * nj1, 1e-8f);
                *reinterpret_cast<float2*>(out + rbase + cloc) = v;
                if (mirror) {
                    tb[rloc * 129 + cloc]     = v.x;
                    tb[rloc * 129 + cloc + 1] = v.y;
                }
            }
        }
    }

    if (mirror) {
        __syncthreads();
        // transposed write: out[(col0+c)*N + row0 + r], r = fast index
        const int r = tid;                          // 0..127
        #pragma unroll 4
        for (int c = 0; c < 128; c++) {
            out[(size_t)(col0 + c) * NROWS + row0 + r] = tb[r * 129 + c];
        }
    }
}

// ============================================================================
// kernel_launch — graph-capturable, allocation-free, no static state
// ============================================================================
extern "C" void kernel_launch(void* const* d_in, const int* in_sizes, int n_in,
                              void* d_out, int out_size) {
    const float* mapping = (const float*)d_in[0];
    float* out = (float*)d_out;

    cudaFuncSetAttribute(cosmat_kernel,
                         cudaFuncAttributeMaxDynamicSharedMemorySize, SMEM_TOTAL);

    prep_kernel<<<NROWS, 128>>>(mapping);
    cosmat_kernel<<<NTRI, 128, SMEM_TOTAL>>>(out);
}

// round 10
// speedup vs baseline: 1.1142x; 1.1142x over previous
#include <cuda_runtime.h>
#include <cuda_bf16.h>
#include <cstdint>

// ============================================================================
// Problem constants
// ============================================================================
#define NROWS 8192
#define DIM   512
#define BM    128
#define BN    128
#define BK    64                 // bf16 elements per K-chunk (= 128 bytes/row)
#define KCH   (DIM / BK)         // 8 chunks
#define NSTAGE 3
#define NT    (NROWS / BM)       // 64 tiles per dim
#define NTRI  (NT * (NT + 1) / 2)          // 2080 upper-triangle tiles

#define TILE_BYTES  (BM * 128)         // 16384: 128 rows x 128B
#define STAGE_BYTES (2 * TILE_BYTES)   // A + B per stage = 32 KB

// SMEM layout (dynamic):
//   [0,512)     row norms (128 f32)
//   [512,1024)  col norms (128 f32)
//   [1024, ...) 3 stages x 32KB tiles
#define OFF_NR   0
#define OFF_NC   512
#define OFF_TILE 1024
#define SMEM_TOTAL (OFF_TILE + NSTAGE * STAGE_BYTES)   // 99328 bytes

// ============================================================================
// Static device scratch (allocation-free rule: __device__ globals)
// ============================================================================
__device__ __align__(1024) __nv_bfloat16 g_A[NROWS * DIM];   // 8 MB bf16 copy
__device__ float g_norm[NROWS];

// ============================================================================
// PTX helpers (portable: compile at compute_103)
// ============================================================================
__device__ __forceinline__ uint32_t smem_u32(const void* p) {
    uint32_t a;
    asm("{ .reg .u64 t; cvta.to.shared.u64 t, %1; cvt.u32.u64 %0, t; }"
        : "=r"(a) : "l"(p));
    return a;
}

__device__ __forceinline__ void ldmatrix_x4(uint32_t& r0, uint32_t& r1,
                                            uint32_t& r2, uint32_t& r3,
                                            uint32_t addr) {
    asm volatile("ldmatrix.sync.aligned.m8n8.x4.shared.b16 {%0,%1,%2,%3}, [%4];"
                 : "=r"(r0), "=r"(r1), "=r"(r2), "=r"(r3) : "r"(addr));
}

__device__ __forceinline__ void mma_bf16(float* c, const uint32_t* a,
                                         uint32_t b0, uint32_t b1) {
    asm volatile(
        "mma.sync.aligned.m16n8k16.row.col.f32.bf16.bf16.f32 "
        "{%0,%1,%2,%3}, {%4,%5,%6,%7}, {%8,%9}, {%0,%1,%2,%3};"
        : "+f"(c[0]), "+f"(c[1]), "+f"(c[2]), "+f"(c[3])
        : "r"(a[0]), "r"(a[1]), "r"(a[2]), "r"(a[3]), "r"(b0), "r"(b1));
}

// SW128-style swizzle: byte offset within a [rows][128B] tile
__device__ __forceinline__ uint32_t swz(uint32_t off) {
    return off ^ ((off >> 3) & 0x70);
}

// ============================================================================
// Prep: fp32 -> bf16 conversion + row norms. One block per row, 128 threads.
// ============================================================================
__global__ void __launch_bounds__(128) prep_kernel(const float* __restrict__ in) {
    int row = blockIdx.x, t = threadIdx.x;
    const float4 v = *reinterpret_cast<const float4*>(in + (size_t)row * DIM + t * 4);
    float s = v.x * v.x + v.y * v.y + v.z * v.z + v.w * v.w;

    __nv_bfloat162 p0 = __float22bfloat162_rn(make_float2(v.x, v.y));
    __nv_bfloat162 p1 = __float22bfloat162_rn(make_float2(v.z, v.w));
    uint32_t u0 = *reinterpret_cast<uint32_t*>(&p0);
    uint32_t u1 = *reinterpret_cast<uint32_t*>(&p1);
    *reinterpret_cast<uint2*>(&g_A[(size_t)row * DIM + t * 4]) = make_uint2(u0, u1);

    #pragma unroll
    for (int off = 16; off > 0; off >>= 1)
        s += __shfl_xor_sync(0xFFFFFFFFu, s, off);
    __shared__ float ss[4];
    if ((t & 31) == 0) ss[t >> 5] = s;
    __syncthreads();
    if (t == 0) g_norm[row] = sqrtf(ss[0] + ss[1] + ss[2] + ss[3]);
}

// ============================================================================
// Async stage loader. A tile always; B tile only when loadB (off-diagonal).
// Each tile [128][64] bf16 = [128][128B], SW128 swizzled. 256 threads.
// ============================================================================
__device__ __forceinline__ void load_stage(uint32_t sb, int tid, int row0, int col0,
                                           int kc, int s, bool loadB) {
    uint32_t stage = sb + OFF_TILE + s * STAGE_BYTES;
    #pragma unroll
    for (int i = 0; i < 4; i++) {
        int idx = tid + i * 256;
        int r = idx >> 3, c = idx & 7;
        const void* g = (const char*)(g_A + (size_t)(row0 + r) * DIM + kc * BK) + c * 16;
        uint32_t off = swz((uint32_t)(r * 128 + c * 16));
        asm volatile("cp.async.cg.shared.global [%0], [%1], 16;\n"
                     :: "r"(stage + off), "l"(g));
    }
    if (loadB) {
        #pragma unroll
        for (int i = 0; i < 4; i++) {
            int idx = tid + i * 256;
            int r = idx >> 3, c = idx & 7;
            const void* g = (const char*)(g_A + (size_t)(col0 + r) * DIM + kc * BK) + c * 16;
            uint32_t off = swz((uint32_t)(r * 128 + c * 16));
            asm volatile("cp.async.cg.shared.global [%0], [%1], 16;\n"
                         :: "r"(stage + TILE_BYTES + off), "l"(g));
        }
    }
    asm volatile("cp.async.commit_group;\n" ::: "memory");
}

// ============================================================================
// Main GEMM + epilogue. Upper-triangle tiles; register-direct mirror stores.
// 256 threads = 8 warps (2 m x 4 n), 64x32 per warp. ONE barrier per K-chunk.
// ============================================================================
__global__ void __launch_bounds__(256, 2) cosmat_kernel(float* __restrict__ out) {
    extern __shared__ char smem[];
    uint32_t sb = smem_u32(smem);
    const int tid = threadIdx.x;
    const int wid = tid >> 5, lane = tid & 31;
    const int warp_m = wid >> 2, warp_n = wid & 3;   // 2 x 4

    // --- decode linear block id -> upper-triangle tile (bi <= bj) ---
    const int t = blockIdx.x;
    int bi = (int)((2.0f * NT + 1.0f
                    - sqrtf((2.0f * NT + 1.0f) * (2.0f * NT + 1.0f) - 8.0f * t))
                   * 0.5f);
    while (bi > 0 && bi * (2 * NT - bi + 1) / 2 > t) bi--;
    while ((bi + 1) * (2 * NT - bi) / 2 <= t) bi++;
    const int bj = bi + (t - bi * (2 * NT - bi + 1) / 2);
    const int row0 = bi * BM, col0 = bj * BN;
    const bool mirror = (bi != bj);

    if (tid < 128) ((float*)(smem + OFF_NR))[tid] = g_norm[row0 + tid];
    else           ((float*)(smem + OFF_NC))[tid - 128] = g_norm[col0 + tid - 128];

    // prologue: fill first 2 stages
    load_stage(sb, tid, row0, col0, 0, 0, mirror);
    load_stage(sb, tid, row0, col0, 1, 1, mirror);

    float acc[4][4][4];
    #pragma unroll
    for (int i = 0; i < 4; i++)
        #pragma unroll
        for (int j = 0; j < 4; j++)
            #pragma unroll
            for (int k = 0; k < 4; k++) acc[i][j][k] = 0.0f;

    const int m0 = warp_m * 64;
    const int n0 = warp_n * 32;

    // per-lane fragment addressing (within-tile)
    const int a_row  = lane & 15;
    const int a_koff = ((lane >> 4) & 1) * 8;
    const int b_row  = (lane & 7) + ((lane >> 4) & 1) * 8;
    const int b_koff = ((lane >> 3) & 1) * 8;
    // diagonal tiles: B reads alias the A tile
    const uint32_t b_tile_off = mirror ? TILE_BYTES : 0u;

    for (int kc = 0; kc < KCH; kc++) {
        const int s = kc % NSTAGE;

        // wait own copies of chunk kc, then single barrier: (a) makes all
        // threads' chunk-kc data visible, (b) guarantees everyone is done
        // reading the stage that load_stage below will overwrite.
        if (kc < KCH - 1) asm volatile("cp.async.wait_group 1;\n" ::: "memory");
        else              asm volatile("cp.async.wait_group 0;\n" ::: "memory");
        __syncthreads();

        if (kc + 2 < KCH)
            load_stage(sb, tid, row0, col0, kc + 2, (kc + 2) % NSTAGE, mirror);

        const uint32_t sa  = sb + OFF_TILE + s * STAGE_BYTES;
        const uint32_t sbb = sa + b_tile_off;

        #pragma unroll
        for (int kq = 0; kq < 4; kq++) {
            const int kb_a = kq * 16 + a_koff;
            const int kb_b = kq * 16 + b_koff;

            uint32_t b[2][4];
            #pragma unroll
            for (int p = 0; p < 2; p++) {
                uint32_t off = swz((uint32_t)((n0 + p * 16 + b_row) * 128 + kb_b * 2));
                ldmatrix_x4(b[p][0], b[p][1], b[p][2], b[p][3], sbb + off);
            }

            // software-pipelined A: load a[mt+1] before consuming a[mt]
            uint32_t ar[2][4];
            {
                uint32_t off = swz((uint32_t)((m0 + a_row) * 128 + kb_a * 2));
                ldmatrix_x4(ar[0][0], ar[0][1], ar[0][2], ar[0][3], sa + off);
            }
            #pragma unroll
            for (int mt = 0; mt < 4; mt++) {
                if (mt < 3) {
                    uint32_t off = swz((uint32_t)((m0 + (mt + 1) * 16 + a_row) * 128
                                                  + kb_a * 2));
                    ldmatrix_x4(ar[(mt + 1) & 1][0], ar[(mt + 1) & 1][1],
                                ar[(mt + 1) & 1][2], ar[(mt + 1) & 1][3], sa + off);
                }
                const uint32_t* a = ar[mt & 1];
                #pragma unroll
                for (int p = 0; p < 2; p++) {
                    mma_bf16(acc[mt][2 * p],     a, b[p][0], b[p][1]);
                    mma_bf16(acc[mt][2 * p + 1], a, b[p][2], b[p][3]);
                }
            }
        }
    }

    // ---- epilogue: cosine distance; direct + register-direct mirror stores ----
    const float* nr = (const float*)(smem + OFF_NR);
    const float* nc = (const float*)(smem + OFF_NC);
    const int lr = lane >> 2;
    const int lc = (lane & 3) * 2;

    #pragma unroll
    for (int mt = 0; mt < 4; mt++) {
        #pragma unroll
        for (int half = 0; half < 2; half++) {
            const int rloc = m0 + mt * 16 + lr + half * 8;
            const float ni = nr[rloc];
            const size_t rbase = (size_t)(row0 + rloc) * NROWS + col0;
            #pragma unroll
            for (int nt = 0; nt < 4; nt++) {
                const int cloc = n0 + nt * 8 + lc;
                const float nj0 = nc[cloc], nj1 = nc[cloc + 1];
                float2 v;
                v.x = 1.0f - acc[mt][nt][2 * half]     / fmaxf(ni * nj0, 1e-8f);
                v.y = 1.0f - acc[mt][nt][2 * half + 1] / fmaxf(ni * nj1, 1e-8f);
                *reinterpret_cast<float2*>(out + rbase + cloc) = v;
                if (mirror) {
                    // transposed element stores: 8 lanes (lr) share a column ->
                    // 8 consecutive rows = one full 32B sector per column.
                    out[(size_t)(col0 + cloc)     * NROWS + (row0 + rloc)] = v.x;
                    out[(size_t)(col0 + cloc + 1) * NROWS + (row0 + rloc)] = v.y;
                }
            }
        }
    }
}

// ============================================================================
// kernel_launch — graph-capturable, allocation-free, no static state
// ============================================================================
extern "C" void kernel_launch(void* const* d_in, const int* in_sizes, int n_in,
                              void* d_out, int out_size) {
    const float* mapping = (const float*)d_in[0];
    float* out = (float*)d_out;

    cudaFuncSetAttribute(cosmat_kernel,
                         cudaFuncAttributeMaxDynamicSharedMemorySize, SMEM_TOTAL);

    prep_kernel<<<NROWS, 128>>>(mapping);
    cosmat_kernel<<<NTRI, 256, SMEM_TOTAL>>>(out);
}